// round 2
// baseline (speedup 1.0000x reference)
#include <cuda_runtime.h>
#include <cuda_bf16.h>
#include <math.h>

#define NN 100000
#define NE 3200000
#define NG 512
#define FOUT 20

// ---------------- scratch (device globals; no allocation allowed) ------------
__device__ int   g_cnt[NN];        // per-dst degree
__device__ int   g_pos[NN];        // scatter cursor
__device__ int   g_off[NN];        // CSR offsets (exclusive scan of g_cnt)
__device__ int   g_esrc[NE];       // CSR: source node per slot
__device__ float g_eew[NE];        // CSR: edge weight per slot
__device__ float g_hA[NN * FOUT];  // ping
__device__ float g_hB[NN * FOUT];  // pong

__device__ __forceinline__ float* bufptr(int sel) {
    return (sel == 0) ? g_hA : g_hB;
}

// ---------------- CSR build ---------------------------------------------------
__global__ void __launch_bounds__(256) zero_kernel() {
    int i = blockIdx.x * blockDim.x + threadIdx.x;
    if (i < NN) { g_cnt[i] = 0; g_pos[i] = 0; }
}

__global__ void __launch_bounds__(256) hist_kernel(const int* __restrict__ dst) {
    int e = blockIdx.x * blockDim.x + threadIdx.x;
    if (e < NE) atomicAdd(&g_cnt[dst[e]], 1);
}

// single-block exclusive scan of g_cnt -> g_off (100000 elements)
__global__ void __launch_bounds__(1024) scan_kernel() {
    const int T  = 1024;
    const int CH = (NN + T - 1) / T;  // 98
    int t    = threadIdx.x;
    int base = t * CH;

    int s = 0;
    for (int j = 0; j < CH; j++) {
        int i = base + j;
        if (i < NN) s += g_cnt[i];
    }

    int lane = t & 31, w = t >> 5;
    __shared__ int wsum[32];

    // inclusive warp scan of s
    int v = s;
    #pragma unroll
    for (int o = 1; o < 32; o <<= 1) {
        int u = __shfl_up_sync(0xffffffffu, v, o);
        if (lane >= o) v += u;
    }
    if (lane == 31) wsum[w] = v;
    __syncthreads();
    if (t < 32) {
        int vv = wsum[t];
        #pragma unroll
        for (int o = 1; o < 32; o <<= 1) {
            int u = __shfl_up_sync(0xffffffffu, vv, o);
            if (t >= o) vv += u;
        }
        wsum[t] = vv;  // inclusive scan of warp totals
    }
    __syncthreads();

    int excl = (v - s) + ((w > 0) ? wsum[w - 1] : 0);
    int run  = excl;
    for (int j = 0; j < CH; j++) {
        int i = base + j;
        if (i < NN) { g_off[i] = run; run += g_cnt[i]; }
    }
}

__global__ void __launch_bounds__(256) scatter_kernel(const int* __restrict__ src,
                                                      const int* __restrict__ dst,
                                                      const float* __restrict__ ew) {
    int e = blockIdx.x * blockDim.x + threadIdx.x;
    if (e >= NE) return;
    int d    = dst[e];
    int slot = g_off[d] + atomicAdd(&g_pos[d], 1);
    g_esrc[slot] = src[e];
    g_eew[slot]  = ew[e];
}

// ---------------- GraphConv layer: CSR gather + tiny GEMM + norm + relu ------
// insel: -1 -> use xext (the raw input x), else bufptr(insel). outsel selects output.
template <int FIN>
__global__ void __launch_bounds__(256) layer_kernel(const float* __restrict__ xext,
                                                    const float* __restrict__ Wrel,
                                                    const float* __restrict__ brel,
                                                    const float* __restrict__ Wroot,
                                                    int insel, int outsel) {
    __shared__ float sWrel[FOUT * FIN];
    __shared__ float sWroot[FOUT * FIN];
    __shared__ float sb[FOUT];

    for (int i = threadIdx.x; i < FOUT * FIN; i += blockDim.x) {
        sWrel[i]  = Wrel[i];
        sWroot[i] = Wroot[i];
    }
    if (threadIdx.x < FOUT) sb[threadIdx.x] = brel[threadIdx.x];
    __syncthreads();

    const float* xin = (insel < 0) ? xext : bufptr(insel);
    float* hout      = bufptr(outsel);

    int n = blockIdx.x * blockDim.x + threadIdx.x;
    if (n >= NN) return;

    float acc[FIN];
    #pragma unroll
    for (int k = 0; k < FIN; k++) acc[k] = 0.0f;

    int s0  = g_off[n];
    int cnt = g_cnt[n];
    for (int j = 0; j < cnt; j++) {
        int   src = g_esrc[s0 + j];
        float w   = g_eew[s0 + j];
        const float* xr = xin + (long)src * FIN;
        #pragma unroll
        for (int k = 0; k < FIN; k++) acc[k] += w * __ldg(xr + k);
    }

    float xi[FIN];
    {
        const float* xr = xin + (long)n * FIN;
        #pragma unroll
        for (int k = 0; k < FIN; k++) xi[k] = xr[k];
    }

    float out[FOUT];
    float ss = 0.0f;
    #pragma unroll
    for (int f = 0; f < FOUT; f++) {
        float v = sb[f];
        #pragma unroll
        for (int k = 0; k < FIN; k++) v += acc[k] * sWrel[f * FIN + k];
        #pragma unroll
        for (int k = 0; k < FIN; k++) v += xi[k] * sWroot[f * FIN + k];
        out[f] = v;
        ss += v * v;
    }

    float nrm = sqrtf(ss);
    float inv = 1.0f / fmaxf(nrm, 1e-12f);
    float* ho = hout + (long)n * FOUT;
    #pragma unroll
    for (int f = 0; f < FOUT; f++) ho[f] = fmaxf(out[f] * inv, 0.0f);
}

// ---------------- pooling + final linear (batch is sorted -> no atomics) -----
__device__ __forceinline__ int lower_bound_i(const int* __restrict__ a, int n, int key) {
    int lo = 0, hi = n;
    while (lo < hi) {
        int m = (lo + hi) >> 1;
        if (a[m] < key) lo = m + 1; else hi = m;
    }
    return lo;
}

__global__ void __launch_bounds__(256) pool_kernel(const int* __restrict__ batch,
                                                   const float* __restrict__ Wlin,
                                                   const float* __restrict__ blin,
                                                   float* __restrict__ out) {
    const float* emb = g_hA;  // layer 3 output lives in g_hA
    int g = blockIdx.x;

    __shared__ int s_lo, s_hi;
    if (threadIdx.x == 0) {
        s_lo = lower_bound_i(batch, NN, g);
        s_hi = lower_bound_i(batch, NN, g + 1);
    }
    __syncthreads();
    int lo = s_lo, hi = s_hi;

    float sm[FOUT], mx[FOUT];
    #pragma unroll
    for (int k = 0; k < FOUT; k++) { sm[k] = 0.0f; mx[k] = 0.0f; }

    for (int i = lo + threadIdx.x; i < hi; i += blockDim.x) {
        const float* r = emb + (long)i * FOUT;
        #pragma unroll
        for (int k = 0; k < FOUT; k++) {
            float v = r[k];
            sm[k] += v;
            mx[k] = fmaxf(mx[k], v);
        }
    }

    // warp reduce
    #pragma unroll
    for (int o = 16; o > 0; o >>= 1) {
        #pragma unroll
        for (int k = 0; k < FOUT; k++) {
            sm[k] += __shfl_down_sync(0xffffffffu, sm[k], o);
            mx[k] = fmaxf(mx[k], __shfl_down_sync(0xffffffffu, mx[k], o));
        }
    }

    __shared__ float ssum[8][FOUT];
    __shared__ float smax[8][FOUT];
    int w = threadIdx.x >> 5, lane = threadIdx.x & 31;
    if (lane == 0) {
        #pragma unroll
        for (int k = 0; k < FOUT; k++) { ssum[w][k] = sm[k]; smax[w][k] = mx[k]; }
    }
    __syncthreads();

    if (threadIdx.x == 0) {
        float fs[FOUT], fm[FOUT];
        #pragma unroll
        for (int k = 0; k < FOUT; k++) { fs[k] = 0.0f; fm[k] = 0.0f; }
        int nw = blockDim.x >> 5;
        for (int ww = 0; ww < nw; ww++)
            for (int k = 0; k < FOUT; k++) {
                fs[k] += ssum[ww][k];
                fm[k] = fmaxf(fm[k], smax[ww][k]);
            }
        float cnt  = (float)(hi - lo);
        float invc = 1.0f / fmaxf(cnt, 1.0f);
        #pragma unroll
        for (int c = 0; c < 2; c++) {
            float v = blin[c];
            for (int k = 0; k < FOUT; k++) v += fm[k] * Wlin[c * 40 + k];
            for (int k = 0; k < FOUT; k++) v += fs[k] * invc * Wlin[c * 40 + 20 + k];
            out[g * 2 + c] = v;
        }
    }
}

// ---------------- launch ------------------------------------------------------
extern "C" void kernel_launch(void* const* d_in, const int* in_sizes, int n_in,
                              void* d_out, int out_size) {
    (void)in_sizes; (void)n_in; (void)out_size;

    const float* x      = (const float*)d_in[0];
    const int*   ei     = (const int*)  d_in[1];   // [2, NE]: row0=src, row1=dst
    const int*   batch  = (const int*)  d_in[2];
    const float* ew     = (const float*)d_in[3];
    const float* W1_rel = (const float*)d_in[4];
    const float* b1_rel = (const float*)d_in[5];
    const float* W1_root= (const float*)d_in[6];
    const float* W2_rel = (const float*)d_in[7];
    const float* b2_rel = (const float*)d_in[8];
    const float* W2_root= (const float*)d_in[9];
    const float* W3_rel = (const float*)d_in[10];
    const float* b3_rel = (const float*)d_in[11];
    const float* W3_root= (const float*)d_in[12];
    const float* W_lin  = (const float*)d_in[13];
    const float* b_lin  = (const float*)d_in[14];
    float* out = (float*)d_out;

    const int*   src = ei;
    const int*   dst = ei + NE;

    const int TB  = 256;
    const int GB_N = (NN + TB - 1) / TB;   // node grid
    const int GB_E = (NE + TB - 1) / TB;   // edge grid

    zero_kernel   <<<GB_N, TB>>>();
    hist_kernel   <<<GB_E, TB>>>(dst);
    scan_kernel   <<<1, 1024>>>();
    scatter_kernel<<<GB_E, TB>>>(src, dst, ew);

    layer_kernel<10><<<GB_N, TB>>>(x, W1_rel, b1_rel, W1_root, -1, 0); // x   -> hA
    layer_kernel<20><<<GB_N, TB>>>(x, W2_rel, b2_rel, W2_root,  0, 1); // hA  -> hB
    layer_kernel<20><<<GB_N, TB>>>(x, W3_rel, b3_rel, W3_root,  1, 0); // hB  -> hA

    pool_kernel<<<NG, 256>>>(batch, W_lin, b_lin, out);
}

// round 3
// speedup vs baseline: 1.4841x; 1.4841x over previous
#include <cuda_runtime.h>
#include <cuda_bf16.h>
#include <math.h>

#define NN 100000
#define NE 3200000
#define NG 512
#define F 20   // hidden width (FOUT of every layer)

// ---------------- scratch (device globals; no allocation allowed) ------------
__device__ int                g_cnt[NN];       // per-dst degree
__device__ int                g_pos[NN];       // scatter cursor (init = offset)
__device__ int                g_off[NN];       // CSR offsets
__device__ int                g_bsum[128];     // block sums for scan
__device__ unsigned long long g_epack[NE];     // CSR payload: (ew_bits<<32)|src
__device__ float              g_z[NN * F];     // rel-transformed features (gather src)
__device__ float              g_r[NN * F];     // root term + bias
__device__ float              g_h[NN * F];     // current node features

// ---------------- CSR build ---------------------------------------------------
__global__ void __launch_bounds__(256) zero_kernel() {
    int i = blockIdx.x * blockDim.x + threadIdx.x;
    if (i < NN) g_cnt[i] = 0;
}

// 4 edges per thread, int4 loads (NE % 4 == 0)
__global__ void __launch_bounds__(256) hist_kernel(const int* __restrict__ dst) {
    int t = blockIdx.x * blockDim.x + threadIdx.x;  // NE/4 threads
    int4 d = *reinterpret_cast<const int4*>(dst + t * 4);
    atomicAdd(&g_cnt[d.x], 1);
    atomicAdd(&g_cnt[d.y], 1);
    atomicAdd(&g_cnt[d.z], 1);
    atomicAdd(&g_cnt[d.w], 1);
}

// ---- 3-phase scan: 98 blocks x 256 threads x 4 elems = 100352 slots ----------
#define SCAN_BLOCKS 98
#define SCAN_CHUNK  1024  // elems per block

__device__ __forceinline__ int block_excl_scan_256(int s, int* out_total) {
    // exclusive scan of per-thread value s across 256 threads
    int lane = threadIdx.x & 31, w = threadIdx.x >> 5;
    int v = s;
    #pragma unroll
    for (int o = 1; o < 32; o <<= 1) {
        int u = __shfl_up_sync(0xffffffffu, v, o);
        if (lane >= o) v += u;
    }
    __shared__ int wsum[8];
    if (lane == 31) wsum[w] = v;
    __syncthreads();
    if (threadIdx.x == 0) {
        int run = 0;
        #pragma unroll
        for (int i = 0; i < 8; i++) { int tmp = wsum[i]; wsum[i] = run; run += tmp; }
    }
    __syncthreads();
    int excl = (v - s) + wsum[w];
    if (out_total) {
        __shared__ int tot;
        if (threadIdx.x == 255) tot = excl + s;
        __syncthreads();
        *out_total = tot;
    }
    return excl;
}

__global__ void __launch_bounds__(256) scan1_kernel() {
    int base = blockIdx.x * SCAN_CHUNK + threadIdx.x * 4;
    int s = 0;
    #pragma unroll
    for (int j = 0; j < 4; j++) {
        int i = base + j;
        if (i < NN) s += g_cnt[i];
    }
    // block reduce
    int lane = threadIdx.x & 31, w = threadIdx.x >> 5;
    #pragma unroll
    for (int o = 16; o > 0; o >>= 1) s += __shfl_down_sync(0xffffffffu, s, o);
    __shared__ int wsum[8];
    if (lane == 0) wsum[w] = s;
    __syncthreads();
    if (threadIdx.x == 0) {
        int tot = 0;
        #pragma unroll
        for (int i = 0; i < 8; i++) tot += wsum[i];
        g_bsum[blockIdx.x] = tot;
    }
}

__global__ void __launch_bounds__(128) scan2_kernel() {
    // exclusive scan of g_bsum[0..SCAN_BLOCKS) in one block
    __shared__ int sh[SCAN_BLOCKS];
    if (threadIdx.x < SCAN_BLOCKS) sh[threadIdx.x] = g_bsum[threadIdx.x];
    __syncthreads();
    if (threadIdx.x == 0) {
        int run = 0;
        for (int i = 0; i < SCAN_BLOCKS; i++) { int t = sh[i]; sh[i] = run; run += t; }
    }
    __syncthreads();
    if (threadIdx.x < SCAN_BLOCKS) g_bsum[threadIdx.x] = sh[threadIdx.x];
}

__global__ void __launch_bounds__(256) scan3_kernel() {
    int base = blockIdx.x * SCAN_CHUNK + threadIdx.x * 4;
    int c[4]; int s = 0;
    #pragma unroll
    for (int j = 0; j < 4; j++) {
        int i = base + j;
        c[j] = (i < NN) ? g_cnt[i] : 0;
        s += c[j];
    }
    int excl = block_excl_scan_256(s, nullptr) + g_bsum[blockIdx.x];
    int run = excl;
    #pragma unroll
    for (int j = 0; j < 4; j++) {
        int i = base + j;
        if (i < NN) { g_off[i] = run; g_pos[i] = run; }
        run += c[j];
    }
}

// 4 edges per thread, vector loads, packed 8B payload store
__global__ void __launch_bounds__(256) scatter_kernel(const int* __restrict__ src,
                                                      const int* __restrict__ dst,
                                                      const float* __restrict__ ew) {
    int t = blockIdx.x * blockDim.x + threadIdx.x;  // NE/4 threads
    int4   sv = *reinterpret_cast<const int4*>(src + t * 4);
    int4   dv = *reinterpret_cast<const int4*>(dst + t * 4);
    float4 wv = *reinterpret_cast<const float4*>(ew + t * 4);

    int s0 = atomicAdd(&g_pos[dv.x], 1);
    int s1 = atomicAdd(&g_pos[dv.y], 1);
    int s2 = atomicAdd(&g_pos[dv.z], 1);
    int s3 = atomicAdd(&g_pos[dv.w], 1);

    g_epack[s0] = ((unsigned long long)__float_as_uint(wv.x) << 32) | (unsigned)sv.x;
    g_epack[s1] = ((unsigned long long)__float_as_uint(wv.y) << 32) | (unsigned)sv.y;
    g_epack[s2] = ((unsigned long long)__float_as_uint(wv.z) << 32) | (unsigned)sv.z;
    g_epack[s3] = ((unsigned long long)__float_as_uint(wv.w) << 32) | (unsigned)sv.w;
}

// ---------------- per-layer transform: z = f@Wrel^T, r = f@Wroot^T + b --------
// insel: -1 -> external x, else g_h
template <int FIN>
__global__ void __launch_bounds__(256) transform_kernel(const float* __restrict__ xext,
                                                        const float* __restrict__ Wrel,
                                                        const float* __restrict__ brel,
                                                        const float* __restrict__ Wroot,
                                                        int insel) {
    __shared__ float sWrel[F * FIN];
    __shared__ float sWroot[F * FIN];
    __shared__ float sb[F];
    for (int i = threadIdx.x; i < F * FIN; i += blockDim.x) {
        sWrel[i]  = Wrel[i];
        sWroot[i] = Wroot[i];
    }
    if (threadIdx.x < F) sb[threadIdx.x] = brel[threadIdx.x];
    __syncthreads();

    const float* fin = (insel < 0) ? xext : g_h;
    int n = blockIdx.x * blockDim.x + threadIdx.x;
    if (n >= NN) return;

    float f[FIN];
    if (FIN == 20) {
        const float4* p = reinterpret_cast<const float4*>(fin + (long)n * FIN);
        #pragma unroll
        for (int q = 0; q < 5; q++) {
            float4 v = p[q];
            f[q * 4 + 0] = v.x; f[q * 4 + 1] = v.y; f[q * 4 + 2] = v.z; f[q * 4 + 3] = v.w;
        }
    } else {  // FIN == 10, rows are 40B / 8B aligned
        const float2* p = reinterpret_cast<const float2*>(fin + (long)n * FIN);
        #pragma unroll
        for (int q = 0; q < 5; q++) {
            float2 v = p[q];
            f[q * 2 + 0] = v.x; f[q * 2 + 1] = v.y;
        }
    }

    float z[F], r[F];
    #pragma unroll
    for (int j = 0; j < F; j++) {
        float a = 0.0f, bsum = sb[j];
        #pragma unroll
        for (int k = 0; k < FIN; k++) {
            a    += f[k] * sWrel[j * FIN + k];
            bsum += f[k] * sWroot[j * FIN + k];
        }
        z[j] = a; r[j] = bsum;
    }

    float4* zp = reinterpret_cast<float4*>(g_z + (long)n * F);
    float4* rp = reinterpret_cast<float4*>(g_r + (long)n * F);
    #pragma unroll
    for (int q = 0; q < 5; q++) {
        zp[q] = make_float4(z[q * 4], z[q * 4 + 1], z[q * 4 + 2], z[q * 4 + 3]);
        rp[q] = make_float4(r[q * 4], r[q * 4 + 1], r[q * 4 + 2], r[q * 4 + 3]);
    }
}

// ---------------- gather: warp per node, lane per feature ---------------------
// h[n] = norm_relu( sum_slots ew * z[src] + r[n] )
__global__ void __launch_bounds__(256) gather_kernel() {
    int warp = (blockIdx.x * blockDim.x + threadIdx.x) >> 5;
    if (warp >= NN) return;
    int lane = threadIdx.x & 31;
    const bool active = lane < F;

    int n   = warp;
    int s0  = g_off[n];
    int cnt = g_cnt[n];

    float acc = 0.0f;
    for (int base = 0; base < cnt; base += 32) {
        int m = min(32, cnt - base);
        unsigned long long pk = 0;
        if (lane < m) pk = g_epack[s0 + base + lane];
        for (int j = 0; j < m; j++) {
            unsigned long long v = __shfl_sync(0xffffffffu, pk, j);
            int   s = (int)(v & 0xffffffffu);
            float w = __uint_as_float((unsigned)(v >> 32));
            if (active) acc += w * __ldg(g_z + (long)s * F + lane);
        }
    }

    float val = active ? (acc + g_r[(long)n * F + lane]) : 0.0f;
    float ss = val * val;
    #pragma unroll
    for (int o = 16; o > 0; o >>= 1) ss += __shfl_xor_sync(0xffffffffu, ss, o);
    float inv = 1.0f / fmaxf(sqrtf(ss), 1e-12f);
    if (active) g_h[(long)n * F + lane] = fmaxf(val * inv, 0.0f);
}

// ---------------- pooling + final linear (batch is sorted -> no atomics) -----
__device__ __forceinline__ int lower_bound_i(const int* __restrict__ a, int n, int key) {
    int lo = 0, hi = n;
    while (lo < hi) {
        int m = (lo + hi) >> 1;
        if (a[m] < key) lo = m + 1; else hi = m;
    }
    return lo;
}

__global__ void __launch_bounds__(256) pool_kernel(const int* __restrict__ batch,
                                                   const float* __restrict__ Wlin,
                                                   const float* __restrict__ blin,
                                                   float* __restrict__ out) {
    const float* emb = g_h;
    int g = blockIdx.x;

    __shared__ int s_lo, s_hi;
    if (threadIdx.x == 0) {
        s_lo = lower_bound_i(batch, NN, g);
        s_hi = lower_bound_i(batch, NN, g + 1);
    }
    __syncthreads();
    int lo = s_lo, hi = s_hi;

    float sm[F], mx[F];
    #pragma unroll
    for (int k = 0; k < F; k++) { sm[k] = 0.0f; mx[k] = 0.0f; }

    for (int i = lo + threadIdx.x; i < hi; i += blockDim.x) {
        const float* r = emb + (long)i * F;
        #pragma unroll
        for (int k = 0; k < F; k++) {
            float v = __ldg(r + k);
            sm[k] += v;
            mx[k] = fmaxf(mx[k], v);
        }
    }

    #pragma unroll
    for (int o = 16; o > 0; o >>= 1) {
        #pragma unroll
        for (int k = 0; k < F; k++) {
            sm[k] += __shfl_down_sync(0xffffffffu, sm[k], o);
            mx[k] = fmaxf(mx[k], __shfl_down_sync(0xffffffffu, mx[k], o));
        }
    }

    __shared__ float ssum[8][F];
    __shared__ float smax[8][F];
    int w = threadIdx.x >> 5, lane = threadIdx.x & 31;
    if (lane == 0) {
        #pragma unroll
        for (int k = 0; k < F; k++) { ssum[w][k] = sm[k]; smax[w][k] = mx[k]; }
    }
    __syncthreads();

    if (threadIdx.x == 0) {
        float fs[F], fm[F];
        #pragma unroll
        for (int k = 0; k < F; k++) { fs[k] = 0.0f; fm[k] = 0.0f; }
        for (int ww = 0; ww < 8; ww++)
            for (int k = 0; k < F; k++) {
                fs[k] += ssum[ww][k];
                fm[k] = fmaxf(fm[k], smax[ww][k]);
            }
        float cnt  = (float)(hi - lo);
        float invc = 1.0f / fmaxf(cnt, 1.0f);
        #pragma unroll
        for (int c = 0; c < 2; c++) {
            float v = blin[c];
            for (int k = 0; k < F; k++) v += fm[k] * Wlin[c * 40 + k];
            for (int k = 0; k < F; k++) v += fs[k] * invc * Wlin[c * 40 + 20 + k];
            out[g * 2 + c] = v;
        }
    }
}

// ---------------- launch ------------------------------------------------------
extern "C" void kernel_launch(void* const* d_in, const int* in_sizes, int n_in,
                              void* d_out, int out_size) {
    (void)in_sizes; (void)n_in; (void)out_size;

    const float* x      = (const float*)d_in[0];
    const int*   ei     = (const int*)  d_in[1];   // [2, NE]: row0=src, row1=dst
    const int*   batch  = (const int*)  d_in[2];
    const float* ew     = (const float*)d_in[3];
    const float* W1_rel = (const float*)d_in[4];
    const float* b1_rel = (const float*)d_in[5];
    const float* W1_root= (const float*)d_in[6];
    const float* W2_rel = (const float*)d_in[7];
    const float* b2_rel = (const float*)d_in[8];
    const float* W2_root= (const float*)d_in[9];
    const float* W3_rel = (const float*)d_in[10];
    const float* b3_rel = (const float*)d_in[11];
    const float* W3_root= (const float*)d_in[12];
    const float* W_lin  = (const float*)d_in[13];
    const float* b_lin  = (const float*)d_in[14];
    float* out = (float*)d_out;

    const int* src = ei;
    const int* dst = ei + NE;

    const int TB = 256;
    const int GB_N  = (NN + TB - 1) / TB;          // 391
    const int GB_E4 = (NE / 4 + TB - 1) / TB;      // 3125
    const int GB_W  = (NN * 32 + TB - 1) / TB;     // warp-per-node grid: 12500

    zero_kernel   <<<GB_N, TB>>>();
    hist_kernel   <<<GB_E4, TB>>>(dst);
    scan1_kernel  <<<SCAN_BLOCKS, TB>>>();
    scan2_kernel  <<<1, 128>>>();
    scan3_kernel  <<<SCAN_BLOCKS, TB>>>();
    scatter_kernel<<<GB_E4, TB>>>(src, dst, ew);

    transform_kernel<10><<<GB_N, TB>>>(x, W1_rel, b1_rel, W1_root, -1);
    gather_kernel<<<GB_W, TB>>>();
    transform_kernel<20><<<GB_N, TB>>>(x, W2_rel, b2_rel, W2_root, 0);
    gather_kernel<<<GB_W, TB>>>();
    transform_kernel<20><<<GB_N, TB>>>(x, W3_rel, b3_rel, W3_root, 0);
    gather_kernel<<<GB_W, TB>>>();

    pool_kernel<<<NG, 256>>>(batch, W_lin, b_lin, out);
}